// round 12
// baseline (speedup 1.0000x reference)
#include <cuda_runtime.h>
#include <cuda_bf16.h>
#include <cstdint>

// Problem constants
#define Bb 8
#define NSEQ 1024
#define DIM 768
#define HEADS 12
#define HD 64
#define TOPK 100
#define SCALE_F 0.125f

#define MROWS (Bb*NSEQ)          // 8192
#define QKV_N (3*DIM)            // 2304
#define NHEAD (Bb*HEADS)         // 96
#define CAP 192

// ---------------- scratch (device-symbol access ONLY from device code) ----
__device__ __align__(16) float g_q[NHEAD*NSEQ*HD];     // fp32, pre-scaled
__device__ __align__(16) float g_k[NHEAD*NSEQ*HD];
__device__ __align__(16) float g_v[NHEAD*NSEQ*HD];
__device__ __align__(16) float g_qhi[NHEAD*NSEQ*HD], g_qlo[NHEAD*NSEQ*HD];
__device__ __align__(16) float g_khi[NHEAD*NSEQ*HD], g_klo[NHEAD*NSEQ*HD];
__device__ __align__(16) float g_wpt_hi[DIM*DIM], g_wpt_lo[DIM*DIM];   // Wproj^T
__device__ __align__(16) float g_ahi[MROWS*DIM], g_alo[MROWS*DIM];     // attn hi/lo
__device__ __align__(16) float g_s[(size_t)NHEAD*NSEQ*NSEQ];
__device__ int   g_idx[(size_t)NHEAD*NSEQ*CAP];
__device__ float g_pv [(size_t)NHEAD*NSEQ*CAP];
__device__ int   g_cnt[NHEAD*NSEQ];

// ---------------- helpers ----------------
#define MMA_TF32(d, a, b)                                                   \
    asm volatile("mma.sync.aligned.m16n8k8.row.col.f32.tf32.tf32.f32 "      \
        "{%0,%1,%2,%3}, {%4,%5,%6,%7}, {%8,%9}, {%0,%1,%2,%3};"             \
        : "+f"((d)[0]), "+f"((d)[1]), "+f"((d)[2]), "+f"((d)[3])            \
        : "r"((a)[0]), "r"((a)[1]), "r"((a)[2]), "r"((a)[3]),               \
          "r"((b)[0]), "r"((b)[1]))

__device__ __forceinline__ void tf32_split(float f, float& hi, float& lo) {
    uint32_t h, l;
    asm("cvt.rna.tf32.f32 %0, %1;" : "=r"(h) : "f"(f));
    float hf = __uint_as_float(h);
    asm("cvt.rna.tf32.f32 %0, %1;" : "=r"(l) : "f"(f - hf));
    hi = hf;
    lo = __uint_as_float(l);
}

// ---------------------------------------------------------------------------
// fp32 SGEMM (R4-PROVEN): tile 128x64x16, micro 8x4, double-buffered.
// mode 0 only here: QKV scatter (q scaled) -> g_q/g_k/g_v
// ---------------------------------------------------------------------------
#define BM 128
#define BN 64
#define BK 16
#define TM 8
#define TN 4

__global__ __launch_bounds__(256)
void sgemm_kernel(const float* __restrict__ A, const float* __restrict__ B,
                  int M, int N, int K)
{
    __shared__ float As[2][BK][BM + 4];
    __shared__ float Bs[2][BK][BN];

    const int bm = blockIdx.y * BM;
    const int bn = blockIdx.x * BN;
    const int tid = threadIdx.x;
    const int tx = tid & 15;
    const int ty = tid >> 4;

    const int ar0 = tid >> 2;
    const int ar1 = (tid + 256) >> 2;
    const int ac4 = tid & 3;
    const int br  = tid >> 4;
    const int bc4 = tid & 15;

    const float* Abase0 = A + (size_t)(bm + ar0) * K + ac4 * 4;
    const float* Abase1 = A + (size_t)(bm + ar1) * K + ac4 * 4;
    const float* Bbase  = B + (size_t)br * N + bn + bc4 * 4;

    float acc[TM][TN];
#pragma unroll
    for (int i = 0; i < TM; i++)
#pragma unroll
        for (int j = 0; j < TN; j++) acc[i][j] = 0.f;

    {
        float4 a0 = *(const float4*)(Abase0);
        float4 a1 = *(const float4*)(Abase1);
        float4 b0 = *(const float4*)(Bbase);
        As[0][ac4*4+0][ar0] = a0.x; As[0][ac4*4+1][ar0] = a0.y;
        As[0][ac4*4+2][ar0] = a0.z; As[0][ac4*4+3][ar0] = a0.w;
        As[0][ac4*4+0][ar1] = a1.x; As[0][ac4*4+1][ar1] = a1.y;
        As[0][ac4*4+2][ar1] = a1.z; As[0][ac4*4+3][ar1] = a1.w;
        *(float4*)&Bs[0][br][bc4 * 4] = b0;
    }
    __syncthreads();

    const int nk = K / BK;
    for (int it = 0; it < nk; it++) {
        const int cur = it & 1;
        float4 pa0, pa1, pb;
        if (it + 1 < nk) {
            int k0 = (it + 1) * BK;
            pa0 = *(const float4*)(Abase0 + k0);
            pa1 = *(const float4*)(Abase1 + k0);
            pb  = *(const float4*)(Bbase + (size_t)k0 * N);
        }

#pragma unroll
        for (int kk = 0; kk < BK; kk++) {
            float a[TM], b[TN];
            float4 a40 = *(const float4*)&As[cur][kk][ty * TM + 0];
            float4 a41 = *(const float4*)&As[cur][kk][ty * TM + 4];
            a[0]=a40.x; a[1]=a40.y; a[2]=a40.z; a[3]=a40.w;
            a[4]=a41.x; a[5]=a41.y; a[6]=a41.z; a[7]=a41.w;
            float4 b4 = *(const float4*)&Bs[cur][kk][tx * TN];
            b[0]=b4.x; b[1]=b4.y; b[2]=b4.z; b[3]=b4.w;
#pragma unroll
            for (int i = 0; i < TM; i++)
#pragma unroll
                for (int j = 0; j < TN; j++)
                    acc[i][j] += a[i] * b[j];
        }

        if (it + 1 < nk) {
            const int nxt = 1 - cur;
            As[nxt][ac4*4+0][ar0] = pa0.x; As[nxt][ac4*4+1][ar0] = pa0.y;
            As[nxt][ac4*4+2][ar0] = pa0.z; As[nxt][ac4*4+3][ar0] = pa0.w;
            As[nxt][ac4*4+0][ar1] = pa1.x; As[nxt][ac4*4+1][ar1] = pa1.y;
            As[nxt][ac4*4+2][ar1] = pa1.z; As[nxt][ac4*4+3][ar1] = pa1.w;
            *(float4*)&Bs[nxt][br][bc4 * 4] = pb;
            __syncthreads();
        }
    }

    // QKV scatter epilogue
#pragma unroll
    for (int i = 0; i < TM; i++) {
        int m  = bm + ty * TM + i;
        int b_ = m >> 10;
        int n_ = m & 1023;
#pragma unroll
        for (int j = 0; j < TN; j++) {
            int col = bn + tx * TN + j;
            int t = col / DIM;
            int r = col - t * DIM;
            int h = r >> 6;
            int d = r & 63;
            float vv = acc[i][j];
            float* dst;
            if (t == 0)      { dst = g_q; vv *= SCALE_F; }
            else if (t == 1)   dst = g_k;
            else               dst = g_v;
            dst[((size_t)((b_ * HEADS + h) << 10) + n_) * HD + d] = vv;
        }
    }
}

// ---------------------------------------------------------------------------
// Split q & k: fp32 -> tf32 hi/lo (device symbols, selector inside)
// ---------------------------------------------------------------------------
__global__ __launch_bounds__(256)
void split_qk_kernel(int n4)
{
    int i = blockIdx.x * 256 + threadIdx.x;
    if (i >= n4) return;
    {
        float4 v = ((const float4*)g_q)[i];
        float4 h4, l4;
        tf32_split(v.x, h4.x, l4.x);
        tf32_split(v.y, h4.y, l4.y);
        tf32_split(v.z, h4.z, l4.z);
        tf32_split(v.w, h4.w, l4.w);
        ((float4*)g_qhi)[i] = h4;
        ((float4*)g_qlo)[i] = l4;
    }
    {
        float4 v = ((const float4*)g_k)[i];
        float4 h4, l4;
        tf32_split(v.x, h4.x, l4.x);
        tf32_split(v.y, h4.y, l4.y);
        tf32_split(v.z, h4.z, l4.z);
        tf32_split(v.w, h4.w, l4.w);
        ((float4*)g_khi)[i] = h4;
        ((float4*)g_klo)[i] = l4;
    }
}

// ---------------------------------------------------------------------------
// Transpose + split W_proj[K][N] -> g_wpt [N][K] tf32 hi/lo
// ---------------------------------------------------------------------------
__global__ __launch_bounds__(256)
void transpose_split_wp(const float* __restrict__ W, int K, int N)
{
    __shared__ float tb[32][33];
    const int tx = threadIdx.x, ty = threadIdx.y;
    const int n0 = blockIdx.x * 32, k0 = blockIdx.y * 32;
#pragma unroll
    for (int i = 0; i < 4; i++)
        tb[ty + i*8][tx] = W[(size_t)(k0 + ty + i*8) * N + n0 + tx];
    __syncthreads();
#pragma unroll
    for (int i = 0; i < 4; i++) {
        float v = tb[tx][ty + i*8];
        int n = n0 + ty + i*8, k = k0 + tx;
        float h, l;
        tf32_split(v, h, l);
        g_wpt_hi[(size_t)n * K + k] = h;
        g_wpt_lo[(size_t)n * K + k] = l;
    }
}

// ---------------------------------------------------------------------------
// 3xTF32 proj GEMM: out[M,DIM] = attn[M,DIM] @ Wp^T + bias
// Block 128x128, K-chunk 16, 512 thr; register-staged double buffer.
// (structure ran correct in R11; A/B from device symbols)
// ---------------------------------------------------------------------------
#define GSTR 20
#define GA_H 0
#define GA_L (128*GSTR*4)
#define GB_H (2*128*GSTR*4)
#define GB_L (3*128*GSTR*4)
#define GBUF (4*128*GSTR*4)           // 40960 B
#define G_SMEM (2*GBUF)               // 81920 B

__global__ __launch_bounds__(512)
void mma_proj_tf32(const float* __restrict__ bias, float* __restrict__ out)
{
    const float* Ahi = g_ahi;
    const float* Alo = g_alo;
    const float* Bhi = g_wpt_hi;
    const float* Blo = g_wpt_lo;
    const int K = DIM;

    extern __shared__ char smc[];
    const int tid  = threadIdx.x;
    const int wid  = tid >> 5;
    const int lane = tid & 31;
    const int gid  = lane >> 2;
    const int tig  = lane & 3;
    const int wm   = wid & 3;
    const int wn   = wid >> 2;
    const int bn   = blockIdx.x * 128;
    const int bm   = blockIdx.y * 128;

    const int lrow = tid >> 2;
    const int lko  = (tid & 3) * 4;
    const float* pAh = Ahi + (size_t)(bm + lrow) * K + lko;
    const float* pAl = Alo + (size_t)(bm + lrow) * K + lko;
    const float* pBh = Bhi + (size_t)(bn + lrow) * K + lko;
    const float* pBl = Blo + (size_t)(bn + lrow) * K + lko;
    const uint32_t soff = (uint32_t)(lrow * GSTR + lko) * 4;

    float d[2][4][4];
#pragma unroll
    for (int mi = 0; mi < 2; mi++)
#pragma unroll
        for (int nj = 0; nj < 4; nj++)
#pragma unroll
            for (int e = 0; e < 4; e++) d[mi][nj][e] = 0.f;

    const int ns = K >> 4;

    {
        *(float4*)(smc + GA_H + soff) = *(const float4*)(pAh);
        *(float4*)(smc + GA_L + soff) = *(const float4*)(pAl);
        *(float4*)(smc + GB_H + soff) = *(const float4*)(pBh);
        *(float4*)(smc + GB_L + soff) = *(const float4*)(pBl);
    }
    __syncthreads();

    for (int s = 0; s < ns; s++) {
        float4 pa0, pa1, pb0, pb1;
        if (s + 1 < ns) {
            const int k0 = (s + 1) << 4;
            pa0 = *(const float4*)(pAh + k0);
            pa1 = *(const float4*)(pAl + k0);
            pb0 = *(const float4*)(pBh + k0);
            pb1 = *(const float4*)(pBl + k0);
        }

        const char* buf = smc + (s & 1) * GBUF;
        const uint32_t* Ah32 = (const uint32_t*)(buf + GA_H);
        const uint32_t* Al32 = (const uint32_t*)(buf + GA_L);
        const uint32_t* Bh32 = (const uint32_t*)(buf + GB_H);
        const uint32_t* Bl32 = (const uint32_t*)(buf + GB_L);

#pragma unroll
        for (int ksub = 0; ksub < 2; ksub++) {
            const int k0c = ksub * 8;
            uint32_t ah[2][4], al[2][4], bh[4][2], bl[4][2];
#pragma unroll
            for (int mi = 0; mi < 2; mi++) {
                int r0 = wm * 32 + mi * 16 + gid;
                ah[mi][0] = Ah32[r0 * GSTR + k0c + tig];
                ah[mi][1] = Ah32[(r0 + 8) * GSTR + k0c + tig];
                ah[mi][2] = Ah32[r0 * GSTR + k0c + tig + 4];
                ah[mi][3] = Ah32[(r0 + 8) * GSTR + k0c + tig + 4];
                al[mi][0] = Al32[r0 * GSTR + k0c + tig];
                al[mi][1] = Al32[(r0 + 8) * GSTR + k0c + tig];
                al[mi][2] = Al32[r0 * GSTR + k0c + tig + 4];
                al[mi][3] = Al32[(r0 + 8) * GSTR + k0c + tig + 4];
            }
#pragma unroll
            for (int nj = 0; nj < 4; nj++) {
                int n = wn * 32 + nj * 8 + gid;
                bh[nj][0] = Bh32[n * GSTR + k0c + tig];
                bh[nj][1] = Bh32[n * GSTR + k0c + tig + 4];
                bl[nj][0] = Bl32[n * GSTR + k0c + tig];
                bl[nj][1] = Bl32[n * GSTR + k0c + tig + 4];
            }
#pragma unroll
            for (int mi = 0; mi < 2; mi++)
#pragma unroll
                for (int nj = 0; nj < 4; nj++) {
                    MMA_TF32(d[mi][nj], ah[mi], bh[nj]);
                    MMA_TF32(d[mi][nj], ah[mi], bl[nj]);
                    MMA_TF32(d[mi][nj], al[mi], bh[nj]);
                }
        }

        if (s + 1 < ns) {
            char* nbuf = smc + ((s + 1) & 1) * GBUF;
            *(float4*)(nbuf + GA_H + soff) = pa0;
            *(float4*)(nbuf + GA_L + soff) = pa1;
            *(float4*)(nbuf + GB_H + soff) = pb0;
            *(float4*)(nbuf + GB_L + soff) = pb1;
            __syncthreads();
        }
    }

#pragma unroll
    for (int mi = 0; mi < 2; mi++)
#pragma unroll
        for (int nj = 0; nj < 4; nj++)
#pragma unroll
            for (int hf = 0; hf < 2; hf++) {
                const int m   = bm + wm * 32 + mi * 16 + gid + hf * 8;
                const int col = bn + wn * 32 + nj * 8 + tig * 2;
                float* dst = out + (size_t)m * DIM + col;
                *(float2*)dst = make_float2(d[mi][nj][hf*2+0] + bias[col],
                                            d[mi][nj][hf*2+1] + bias[col+1]);
            }
}

// ---------------------------------------------------------------------------
// 3xTF32 S-GEMM (PROVEN): S = Q @ K^T per head, K=64 smem-resident,
// reads precomputed hi/lo via device symbols.
// ---------------------------------------------------------------------------
#define SSTR 68
#define S_SMEM (4*128*SSTR*4)     // 139264 B

__global__ __launch_bounds__(512)
void mma_s_tf32()
{
    extern __shared__ float sm[];
    float* Qh = sm;
    float* Ql = sm + 128 * SSTR;
    float* Kh = sm + 2 * 128 * SSTR;
    float* Kl = sm + 3 * 128 * SSTR;

    const int tid  = threadIdx.x;
    const int wid  = tid >> 5;
    const int lane = tid & 31;
    const int gid  = lane >> 2;
    const int tig  = lane & 3;
    const int wm   = wid & 3;
    const int wn   = wid >> 2;
    const int bm   = blockIdx.y * 128;
    const int bn   = blockIdx.x * 128;
    const int head = blockIdx.z;

    const size_t off = (size_t)head * NSEQ * HD;

#pragma unroll
    for (int t = 0; t < 4; t++) {
        int id  = tid + t * 512;
        int row = id >> 4;
        int c4  = (id & 15) * 4;
        size_t gq = off + (size_t)(bm + row) * HD + c4;
        size_t gk = off + (size_t)(bn + row) * HD + c4;
        *(float4*)&Qh[row * SSTR + c4] = *(const float4*)(g_qhi + gq);
        *(float4*)&Ql[row * SSTR + c4] = *(const float4*)(g_qlo + gq);
        *(float4*)&Kh[row * SSTR + c4] = *(const float4*)(g_khi + gk);
        *(float4*)&Kl[row * SSTR + c4] = *(const float4*)(g_klo + gk);
    }
    __syncthreads();

    const uint32_t* Qh32 = (const uint32_t*)Qh;
    const uint32_t* Ql32 = (const uint32_t*)Ql;
    const uint32_t* Kh32 = (const uint32_t*)Kh;
    const uint32_t* Kl32 = (const uint32_t*)Kl;

    float d[2][4][4];
#pragma unroll
    for (int mi = 0; mi < 2; mi++)
#pragma unroll
        for (int nj = 0; nj < 4; nj++)
#pragma unroll
            for (int e = 0; e < 4; e++) d[mi][nj][e] = 0.f;

#pragma unroll
    for (int ks = 0; ks < 8; ks++) {
        const int k0 = ks * 8;
        uint32_t ah[2][4], al[2][4], bh[4][2], bl[4][2];
#pragma unroll
        for (int mi = 0; mi < 2; mi++) {
            int r0 = wm * 32 + mi * 16 + gid;
            ah[mi][0] = Qh32[r0 * SSTR + k0 + tig];
            ah[mi][1] = Qh32[(r0 + 8) * SSTR + k0 + tig];
            ah[mi][2] = Qh32[r0 * SSTR + k0 + tig + 4];
            ah[mi][3] = Qh32[(r0 + 8) * SSTR + k0 + tig + 4];
            al[mi][0] = Ql32[r0 * SSTR + k0 + tig];
            al[mi][1] = Ql32[(r0 + 8) * SSTR + k0 + tig];
            al[mi][2] = Ql32[r0 * SSTR + k0 + tig + 4];
            al[mi][3] = Ql32[(r0 + 8) * SSTR + k0 + tig + 4];
        }
#pragma unroll
        for (int nj = 0; nj < 4; nj++) {
            int n = wn * 32 + nj * 8 + gid;
            bh[nj][0] = Kh32[n * SSTR + k0 + tig];
            bh[nj][1] = Kh32[n * SSTR + k0 + tig + 4];
            bl[nj][0] = Kl32[n * SSTR + k0 + tig];
            bl[nj][1] = Kl32[n * SSTR + k0 + tig + 4];
        }
#pragma unroll
        for (int mi = 0; mi < 2; mi++)
#pragma unroll
            for (int nj = 0; nj < 4; nj++) {
                MMA_TF32(d[mi][nj], ah[mi], bh[nj]);
                MMA_TF32(d[mi][nj], ah[mi], bl[nj]);
                MMA_TF32(d[mi][nj], al[mi], bh[nj]);
            }
    }

    float* sdst = g_s + (size_t)head * NSEQ * NSEQ;
#pragma unroll
    for (int mi = 0; mi < 2; mi++)
#pragma unroll
        for (int nj = 0; nj < 4; nj++)
#pragma unroll
            for (int hf = 0; hf < 2; hf++) {
                const int m   = bm + wm * 32 + mi * 16 + gid + hf * 8;
                const int col = bn + wn * 32 + nj * 8 + tig * 2;
                *(float2*)(sdst + (size_t)m * NSEQ + col) =
                    make_float2(d[mi][nj][hf * 2 + 0], d[mi][nj][hf * 2 + 1]);
            }
}

// ---------------------------------------------------------------------------
// top-k threshold + masked softmax + compaction (PROVEN)
// ---------------------------------------------------------------------------
__device__ __forceinline__ float ord2f(unsigned k) {
    unsigned u = (k & 0x80000000u) ? (k & 0x7FFFFFFFu) : ~k;
    return __uint_as_float(u);
}

__global__ __launch_bounds__(256)
void topk_kernel()
{
    const int head = blockIdx.y;
    const int warp = threadIdx.x >> 5;
    const int lane = threadIdx.x & 31;
    const int n    = blockIdx.x * 8 + warp;
    const size_t rbase = (size_t)head * NSEQ + n;
    const float* srow = g_s + rbase * NSEQ;

    float s[32];
#pragma unroll
    for (int i = 0; i < 32; i++) s[i] = srow[i * 32 + lane];

    unsigned lo = 0x007FFFFFu;
    unsigned hi = 0xFF800000u;
    while (lo < hi) {
        unsigned mid = lo + ((hi - lo + 1u) >> 1);
        float t = ord2f(mid);
        int cnt = 0;
#pragma unroll
        for (int i = 0; i < 32; i++) cnt += (s[i] >= t) ? 1 : 0;
#pragma unroll
        for (int o = 16; o > 0; o >>= 1)
            cnt += __shfl_xor_sync(0xffffffffu, cnt, o);
        if (cnt >= TOPK) lo = mid; else hi = mid - 1u;
    }
    const float kth = ord2f(lo);

    float m = s[0];
#pragma unroll
    for (int i = 1; i < 32; i++) m = fmaxf(m, s[i]);
#pragma unroll
    for (int o = 16; o > 0; o >>= 1)
        m = fmaxf(m, __shfl_xor_sync(0xffffffffu, m, o));

    float sum = 0.f;
    float p[32];
#pragma unroll
    for (int i = 0; i < 32; i++) {
        bool keep = (s[i] >= kth);
        p[i] = keep ? __expf(s[i] - m) : 0.f;
        sum += p[i];
    }
#pragma unroll
    for (int o = 16; o > 0; o >>= 1)
        sum += __shfl_xor_sync(0xffffffffu, sum, o);
    const float inv = 1.f / sum;

    int* oidx = g_idx + rbase * CAP;
    float* opv = g_pv + rbase * CAP;
    int base = 0;
#pragma unroll
    for (int i = 0; i < 32; i++) {
        bool keep = (p[i] > 0.f);
        unsigned msk = __ballot_sync(0xffffffffu, keep);
        int pos = base + __popc(msk & ((1u << lane) - 1u));
        if (keep && pos < CAP) {
            oidx[pos] = i * 32 + lane;
            opv[pos]  = p[i] * inv;
        }
        base += __popc(msk);
    }
    if (lane == 0) g_cnt[rbase] = (base < CAP) ? base : CAP;
}

// ---------------------------------------------------------------------------
// sparse PV (PROVEN) -> attn hi/lo tf32 split (device symbols)
// ---------------------------------------------------------------------------
__global__ __launch_bounds__(256)
void pv_sparse_kernel()
{
    __shared__ int   sj[8][CAP];
    __shared__ float spv[8][CAP];

    const int head = blockIdx.y;
    const int warp = threadIdx.x >> 5;
    const int lane = threadIdx.x & 31;
    const int n    = blockIdx.x * 8 + warp;
    const size_t rbase = (size_t)head * NSEQ + n;

    const int cnt = g_cnt[rbase];
    const int* oidx = g_idx + rbase * CAP;
    const float* opv = g_pv + rbase * CAP;
    for (int i = lane; i < cnt; i += 32) {
        sj[warp][i]  = oidx[i];
        spv[warp][i] = opv[i];
    }
    __syncwarp();

    const float* V = g_v + (size_t)head * NSEQ * HD;
    float2 acc = make_float2(0.f, 0.f);
    const int d2 = lane * 2;

    int i = 0;
    for (; i + 4 <= cnt; i += 4) {
        int   j0 = sj[warp][i+0], j1 = sj[warp][i+1];
        int   j2 = sj[warp][i+2], j3 = sj[warp][i+3];
        float p0 = spv[warp][i+0], p1 = spv[warp][i+1];
        float p2 = spv[warp][i+2], p3 = spv[warp][i+3];
        float2 v0 = *(const float2*)(V + (size_t)j0 * HD + d2);
        float2 v1 = *(const float2*)(V + (size_t)j1 * HD + d2);
        float2 v2 = *(const float2*)(V + (size_t)j2 * HD + d2);
        float2 v3 = *(const float2*)(V + (size_t)j3 * HD + d2);
        acc.x += p0*v0.x + p1*v1.x + p2*v2.x + p3*v3.x;
        acc.y += p0*v0.y + p1*v1.y + p2*v2.y + p3*v3.y;
    }
    for (; i < cnt; i++) {
        int j = sj[warp][i];
        float pp = spv[warp][i];
        float2 v = *(const float2*)(V + (size_t)j * HD + d2);
        acc.x += pp * v.x;
        acc.y += pp * v.y;
    }

    const int b = head / HEADS;
    const int h = head - b * HEADS;
    const size_t o = ((size_t)(b * NSEQ + n)) * DIM + h * HD + d2;
    float h0, l0, h1, l1;
    tf32_split(acc.x, h0, l0);
    tf32_split(acc.y, h1, l1);
    *(float2*)(g_ahi + o) = make_float2(h0, h1);
    *(float2*)(g_alo + o) = make_float2(l0, l1);
}

// ---------------------------------------------------------------------------
extern "C" void kernel_launch(void* const* d_in, const int* in_sizes, int n_in,
                              void* d_out, int out_size)
{
    const float* x      = (const float*)d_in[0];
    const float* w_qkv  = (const float*)d_in[1];
    const float* w_proj = (const float*)d_in[2];
    const float* b_proj = (const float*)d_in[3];
    float* out = (float*)d_out;

    cudaFuncSetAttribute(mma_proj_tf32,
                         cudaFuncAttributeMaxDynamicSharedMemorySize, G_SMEM);
    cudaFuncSetAttribute(mma_s_tf32,
                         cudaFuncAttributeMaxDynamicSharedMemorySize, S_SMEM);

    // 0) proj weight transpose+split (independent of QKV)
    transpose_split_wp<<<dim3(DIM / 32, DIM / 32), dim3(32, 8)>>>(w_proj, DIM, DIM);

    // 1) QKV GEMM (fp32, PROVEN) + scatter — q/k precision preserved for top-k
    sgemm_kernel<<<dim3(QKV_N / BN, MROWS / BM), 256>>>(
        x, w_qkv, MROWS, QKV_N, DIM);

    // 1b) split q/k -> tf32 hi/lo
    split_qk_kernel<<<(NHEAD * NSEQ * HD / 4 + 255) / 256, 256>>>(NHEAD * NSEQ * HD / 4);

    // 2a) S = Q @ K^T per head (3xTF32, PROVEN)
    mma_s_tf32<<<dim3(NSEQ / 128, NSEQ / 128, NHEAD), 512, S_SMEM>>>();

    // 2b) top-k + softmax + compaction
    topk_kernel<<<dim3(NSEQ / 8, NHEAD), 256>>>();

    // 2c) sparse PV gather -> attn hi/lo
    pv_sparse_kernel<<<dim3(NSEQ / 8, NHEAD), 256>>>();

    // 3) output projection + bias (3xTF32)
    mma_proj_tf32<<<dim3(DIM / 128, MROWS / 128), 512, G_SMEM>>>(b_proj, out);
}